// round 1
// baseline (speedup 1.0000x reference)
#include <cuda_runtime.h>
#include <math.h>

#define HIDDEN   2048
#define GATE_IN  2608
#define GATE_HID 1024
#define NH       16
#define HD       128
#define NP       5
#define OUT_DIM  80     // NH * NP
#define MAX_NT   8192
#define TOK      4

// Static scratch (no allocations allowed in kernel_launch).
__device__ float g_gate[(size_t)MAX_NT * GATE_IN];   // router input  [NT, 2608]
__device__ float g_h[(size_t)MAX_NT * GATE_HID];     // GELU(GEMM1)   [NT, 1024]
__device__ float g_probs[(size_t)MAX_NT * OUT_DIM];  // probs         [NT, 80]

__device__ __forceinline__ float wredsum(float v) {
#pragma unroll
    for (int o = 16; o; o >>= 1) v += __shfl_xor_sync(0xffffffffu, v, o);
    return v;
}

// ---------------------------------------------------------------------------
// Kernel A: per-token path stats + gate_input assembly.
// One block per token, 16 warps = 16 heads. Each warp holds all 5 path
// vectors (4 floats/lane/path) in registers; 25 warp reductions give
// sums/sumsq/sumabs (5 each) + 10 pairwise dots.
// ---------------------------------------------------------------------------
__global__ void __launch_bounds__(512) stats_kernel(
    const float* __restrict__ hidden,
    const float* __restrict__ p0, const float* __restrict__ p1,
    const float* __restrict__ p2, const float* __restrict__ p3,
    const float* __restrict__ p4)
{
    const int t   = blockIdx.x;
    const int tid = threadIdx.x;
    float* gate = g_gate + (size_t)t * GATE_IN;

    // copy hidden_states -> gate[0:2048)  (512 threads * 1 float4)
    reinterpret_cast<float4*>(gate)[tid] =
        (reinterpret_cast<const float4*>(hidden) + (size_t)t * (HIDDEN / 4))[tid];

    const int w = tid >> 5, lane = tid & 31;
    const float* pp[NP] = {p0, p1, p2, p3, p4};
    const size_t base = (size_t)t * (NH * HD) + (size_t)w * HD + lane * 4;

    float4 v[NP];
#pragma unroll
    for (int p = 0; p < NP; p++) v[p] = *reinterpret_cast<const float4*>(pp[p] + base);

    float vals[25];
#pragma unroll
    for (int p = 0; p < NP; p++) {
        vals[p]      = v[p].x + v[p].y + v[p].z + v[p].w;
        vals[5 + p]  = v[p].x * v[p].x + v[p].y * v[p].y + v[p].z * v[p].z + v[p].w * v[p].w;
        vals[10 + p] = fabsf(v[p].x) + fabsf(v[p].y) + fabsf(v[p].z) + fabsf(v[p].w);
    }
    {
        int k = 15;
#pragma unroll
        for (int p = 0; p < NP; p++)
#pragma unroll
            for (int q = p + 1; q < NP; q++) {
                vals[k++] = v[p].x * v[q].x + v[p].y * v[q].y +
                            v[p].z * v[q].z + v[p].w * v[q].w;
            }
    }
#pragma unroll
    for (int i = 0; i < 25; i++) vals[i] = wredsum(vals[i]);

    if (lane == 0) {
        const float inv = 1.0f / 128.0f;
        float sq[NP], l2[NP];
#pragma unroll
        for (int p = 0; p < NP; p++) {
            float mean = vals[p] * inv;
            sq[p] = vals[5 + p];
            l2[p] = sqrtf(sq[p]);
            float var = sq[p] * inv - mean * mean;
            float am  = vals[10 + p] * inv;
            float* s = gate + HIDDEN + w * (NP * 4) + p * 4;
            s[0] = mean; s[1] = var; s[2] = am; s[3] = l2[p];
            gate[HIDDEN + NH * NP * 4 + w * NP + p] = l2[p];  // norms at 2368
        }
        int kk = 0;
#pragma unroll
        for (int p = 0; p < NP; p++)
#pragma unroll
            for (int q = p + 1; q < NP; q++) {
                float d2 = sq[p] + sq[q] - 2.0f * vals[15 + kk];
                gate[2448 + w * 10 + kk] = sqrtf(fmaxf(d2, 0.0f));
                kk++;
            }
    }
}

// ---------------------------------------------------------------------------
// Kernel B: GEMM1  h = GELU(gate[NT,2608] @ W1^T[2608,1024] + b1)
// Classic 128x128x16 SMEM-tiled SGEMM, 256 threads, 8x8 per-thread tile.
// Dimensions are exact multiples (NT%128==0, 1024%128==0, 2608%16==0).
// ---------------------------------------------------------------------------
__global__ void __launch_bounds__(256) gemm1_gelu_kernel(
    const float* __restrict__ W1, const float* __restrict__ b1)
{
    __shared__ float As[16][128];
    __shared__ float Bs[16][128];

    const int tid  = threadIdx.x;
    const int trow = tid / 16;        // 0..15
    const int tcol = tid % 16;        // 0..15
    const int lrow = tid >> 2;        // 0..63
    const int lcol = (tid & 3) * 4;   // 0,4,8,12

    const float* A = g_gate + (size_t)blockIdx.y * 128 * GATE_IN;
    const float* B = W1     + (size_t)blockIdx.x * 128 * GATE_IN;

    float acc[8][8];
#pragma unroll
    for (int i = 0; i < 8; i++)
#pragma unroll
        for (int j = 0; j < 8; j++) acc[i][j] = 0.0f;

    for (int k0 = 0; k0 < GATE_IN; k0 += 16) {
#pragma unroll
        for (int i = 0; i < 2; i++) {
            const int r = lrow + i * 64;
            float4 a = *reinterpret_cast<const float4*>(A + (size_t)r * GATE_IN + k0 + lcol);
            As[lcol + 0][r] = a.x; As[lcol + 1][r] = a.y;
            As[lcol + 2][r] = a.z; As[lcol + 3][r] = a.w;
            float4 b = *reinterpret_cast<const float4*>(B + (size_t)r * GATE_IN + k0 + lcol);
            Bs[lcol + 0][r] = b.x; Bs[lcol + 1][r] = b.y;
            Bs[lcol + 2][r] = b.z; Bs[lcol + 3][r] = b.w;
        }
        __syncthreads();
#pragma unroll
        for (int kk = 0; kk < 16; kk++) {
            float ar[8], br[8];
#pragma unroll
            for (int i = 0; i < 8; i++) ar[i] = As[kk][trow * 8 + i];
#pragma unroll
            for (int j = 0; j < 8; j++) br[j] = Bs[kk][tcol * 8 + j];
#pragma unroll
            for (int i = 0; i < 8; i++)
#pragma unroll
                for (int j = 0; j < 8; j++) acc[i][j] += ar[i] * br[j];
        }
        __syncthreads();
    }

    const int    col0 = blockIdx.x * 128 + tcol * 8;
    const size_t row0 = (size_t)blockIdx.y * 128 + trow * 8;
    float bb[8];
#pragma unroll
    for (int j = 0; j < 8; j++) bb[j] = b1[col0 + j];
#pragma unroll
    for (int i = 0; i < 8; i++) {
        float* dst = g_h + (row0 + i) * GATE_HID + col0;
#pragma unroll
        for (int j = 0; j < 8; j++) {
            float x = acc[i][j] + bb[j];
            // exact GELU: 0.5*x*(1+erf(x/sqrt(2)))
            dst[j] = 0.5f * x * (1.0f + erff(x * 0.70710678118654752f));
        }
    }
}

// ---------------------------------------------------------------------------
// Kernel C: GEMM2 (K=1024, N=80) + softmax/temp + clip(0.02) + renorm.
// TOK=4 tokens per block amortize W2 reads; h rows staged in SMEM.
// ---------------------------------------------------------------------------
__global__ void __launch_bounds__(256) gemm2_softmax_kernel(
    const float* __restrict__ W2, const float* __restrict__ b2,
    const float* __restrict__ log_temp)
{
    __shared__ float hs[TOK][GATE_HID];
    __shared__ float lg[TOK][OUT_DIM];

    const int tid   = threadIdx.x;
    const int tbase = blockIdx.x * TOK;

#pragma unroll
    for (int i = 0; i < TOK; i++) {
        reinterpret_cast<float4*>(hs[i])[tid] =
            reinterpret_cast<const float4*>(g_h + (size_t)(tbase + i) * GATE_HID)[tid];
    }
    __syncthreads();

    const int w = tid >> 5, lane = tid & 31;
    for (int j = w; j < OUT_DIM; j += 8) {
        const float4* wr = reinterpret_cast<const float4*>(W2 + (size_t)j * GATE_HID);
        float s0 = 0.f, s1 = 0.f, s2 = 0.f, s3 = 0.f;
#pragma unroll
        for (int i = 0; i < 8; i++) {
            float4 b  = wr[lane + i * 32];
            float4 a0 = reinterpret_cast<float4*>(hs[0])[lane + i * 32];
            float4 a1 = reinterpret_cast<float4*>(hs[1])[lane + i * 32];
            float4 a2 = reinterpret_cast<float4*>(hs[2])[lane + i * 32];
            float4 a3 = reinterpret_cast<float4*>(hs[3])[lane + i * 32];
            s0 += a0.x * b.x + a0.y * b.y + a0.z * b.z + a0.w * b.w;
            s1 += a1.x * b.x + a1.y * b.y + a1.z * b.z + a1.w * b.w;
            s2 += a2.x * b.x + a2.y * b.y + a2.z * b.z + a2.w * b.w;
            s3 += a3.x * b.x + a3.y * b.y + a3.z * b.z + a3.w * b.w;
        }
        s0 = wredsum(s0); s1 = wredsum(s1); s2 = wredsum(s2); s3 = wredsum(s3);
        if (lane == 0) {
            float bj = b2[j];
            lg[0][j] = s0 + bj; lg[1][j] = s1 + bj;
            lg[2][j] = s2 + bj; lg[3][j] = s3 + bj;
        }
    }
    __syncthreads();

    if (tid < TOK * NH) {
        const int tt = tid >> 4, h = tid & 15;
        const float invt = expf(-log_temp[h]);   // 1/exp(log_temp)
        float l[NP], mx = -1e30f;
#pragma unroll
        for (int p = 0; p < NP; p++) { l[p] = lg[tt][h * NP + p] * invt; mx = fmaxf(mx, l[p]); }
        float e[NP], se = 0.f;
#pragma unroll
        for (int p = 0; p < NP; p++) { e[p] = expf(l[p] - mx); se += e[p]; }
        const float ise = 1.0f / se;
        float pr[NP], s2s = 0.f;
#pragma unroll
        for (int p = 0; p < NP; p++) { pr[p] = fmaxf(e[p] * ise, 0.02f); s2s += pr[p]; }
        const float is2 = 1.0f / s2s;
        float* dst = g_probs + (size_t)(tbase + tt) * OUT_DIM + h * NP;
#pragma unroll
        for (int p = 0; p < NP; p++) dst[p] = pr[p] * is2;
    }
}

// ---------------------------------------------------------------------------
// Kernel D: weighted path combine (float4-vectorized, memory-bound).
// ---------------------------------------------------------------------------
__global__ void output_kernel(
    const float* __restrict__ p0, const float* __restrict__ p1,
    const float* __restrict__ p2, const float* __restrict__ p3,
    const float* __restrict__ p4, float* __restrict__ out, int n4)
{
    const int v = blockIdx.x * blockDim.x + threadIdx.x;
    if (v >= n4) return;
    const int t = v >> 9;          // 2048 floats per token / 4
    const int h = (v >> 5) & 15;   // 128 floats per head / 4
    const float* pb = g_probs + (size_t)t * OUT_DIM + h * NP;
    const float w0 = pb[0], w1 = pb[1], w2 = pb[2], w3 = pb[3], w4 = pb[4];
    const float4 a0 = reinterpret_cast<const float4*>(p0)[v];
    const float4 a1 = reinterpret_cast<const float4*>(p1)[v];
    const float4 a2 = reinterpret_cast<const float4*>(p2)[v];
    const float4 a3 = reinterpret_cast<const float4*>(p3)[v];
    const float4 a4 = reinterpret_cast<const float4*>(p4)[v];
    float4 o;
    o.x = a0.x * w0 + a1.x * w1 + a2.x * w2 + a3.x * w3 + a4.x * w4;
    o.y = a0.y * w0 + a1.y * w1 + a2.y * w2 + a3.y * w3 + a4.y * w4;
    o.z = a0.z * w0 + a1.z * w1 + a2.z * w2 + a3.z * w3 + a4.z * w4;
    o.w = a0.w * w0 + a1.w * w1 + a2.w * w2 + a3.w * w3 + a4.w * w4;
    reinterpret_cast<float4*>(out)[v] = o;
}

__global__ void zero_tail_kernel(float* out, int start, int total)
{
    const int i = start + blockIdx.x * blockDim.x + threadIdx.x;
    if (i < total) out[i] = 0.0f;   // reg_loss = 0.0 (eval mode)
}

// ---------------------------------------------------------------------------
extern "C" void kernel_launch(void* const* d_in, const int* in_sizes, int n_in,
                              void* d_out, int out_size)
{
    const float* hidden = (const float*)d_in[0];
    const float* p0 = (const float*)d_in[1];
    const float* p1 = (const float*)d_in[2];
    const float* p2 = (const float*)d_in[3];
    const float* p3 = (const float*)d_in[4];
    const float* p4 = (const float*)d_in[5];
    const float* W1 = (const float*)d_in[6];
    const float* b1 = (const float*)d_in[7];
    const float* W2 = (const float*)d_in[8];
    const float* b2 = (const float*)d_in[9];
    const float* lt = (const float*)d_in[10];

    const int NT = in_sizes[0] / HIDDEN;   // 8192 (B*L)

    stats_kernel<<<NT, 512>>>(hidden, p0, p1, p2, p3, p4);

    dim3 g1(GATE_HID / 128, NT / 128);
    gemm1_gelu_kernel<<<g1, 256>>>(W1, b1);

    gemm2_softmax_kernel<<<NT / TOK, 256>>>(W2, b2, lt);

    const int n4 = NT * (NH * HD) / 4;
    output_kernel<<<(n4 + 255) / 256, 256>>>(p0, p1, p2, p3, p4, (float*)d_out, n4);

    const int nout = NT * NH * HD;
    if (out_size > nout) {
        const int extra = out_size - nout;
        zero_tail_kernel<<<(extra + 255) / 256, 256>>>((float*)d_out, nout, out_size);
    }
}

// round 4
// speedup vs baseline: 2.6037x; 2.6037x over previous
#include <cuda_runtime.h>
#include <cstdint>
#include <math.h>

#define HIDDEN      2048
#define GATE_IN     2608
#define GATE_IN_PAD 2624        // 82 * 32
#define GATE_HID    1024
#define NH          16
#define HD          128
#define NP          5
#define OUT_DIM     80
#define MAX_NT      8192
#define TOK         4

// GEMM1 tiling (mma.sync tf32)
#define KCHUNK      32
#define NCHUNK      (GATE_IN_PAD / KCHUNK)   // 82
#define SM_STRIDE   36                        // padded floats per row
#define ABUF_FLOATS (128 * SM_STRIDE)         // 4608
#define ABUF_BYTES  (ABUF_FLOATS * 4)         // 18432
#define GEMM1_SMEM  (4 * ABUF_BYTES)          // 73728 (A0,A1,B0,B1)

// Static scratch
__device__ float g_gate[(size_t)MAX_NT * GATE_IN_PAD];
__device__ float g_w1p[(size_t)GATE_HID * GATE_IN_PAD];
__device__ float g_h[(size_t)MAX_NT * GATE_HID];
__device__ float g_probs[(size_t)MAX_NT * OUT_DIM];

// ---------------------------------------------------------------------------
// helpers
// ---------------------------------------------------------------------------
__device__ __forceinline__ float wredsum(float v) {
#pragma unroll
    for (int o = 16; o; o >>= 1) v += __shfl_xor_sync(0xffffffffu, v, o);
    return v;
}
__device__ __forceinline__ float tf32r(float x) {
    float y;
    asm("cvt.rna.tf32.f32 %0, %1;" : "=f"(y) : "f"(x));
    return y;
}
__device__ __forceinline__ void cp_async16(uint32_t dst, const void* src) {
    asm volatile("cp.async.cg.shared.global [%0], [%1], 16;" :: "r"(dst), "l"(src));
}
__device__ __forceinline__ uint32_t smem_u32(const void* p) {
    uint32_t a;
    asm("{ .reg .u64 t; cvta.to.shared.u64 t, %1; cvt.u32.u64 %0, t; }" : "=r"(a) : "l"(p));
    return a;
}
__device__ __forceinline__ float gelu(float x) {
    return 0.5f * x * (1.0f + erff(x * 0.70710678118654752f));
}
__device__ __forceinline__ void mma_tf32_16x8x8(float c[4],
                                                uint32_t a0, uint32_t a1,
                                                uint32_t a2, uint32_t a3,
                                                uint32_t b0, uint32_t b1) {
    asm("mma.sync.aligned.m16n8k8.row.col.f32.tf32.tf32.f32 "
        "{%0,%1,%2,%3}, {%4,%5,%6,%7}, {%8,%9}, {%0,%1,%2,%3};"
        : "+f"(c[0]), "+f"(c[1]), "+f"(c[2]), "+f"(c[3])
        : "r"(a0), "r"(a1), "r"(a2), "r"(a3), "r"(b0), "r"(b1));
}

// ---------------------------------------------------------------------------
// Kernel A: per-token path stats + gate_input assembly (tf32-rounded).
// ---------------------------------------------------------------------------
__global__ void __launch_bounds__(512) stats_kernel(
    const float* __restrict__ hidden,
    const float* __restrict__ p0, const float* __restrict__ p1,
    const float* __restrict__ p2, const float* __restrict__ p3,
    const float* __restrict__ p4)
{
    const int t   = blockIdx.x;
    const int tid = threadIdx.x;
    float* gate = g_gate + (size_t)t * GATE_IN_PAD;

    {
        float4 v = (reinterpret_cast<const float4*>(hidden) + (size_t)t * (HIDDEN / 4))[tid];
        v.x = tf32r(v.x); v.y = tf32r(v.y); v.z = tf32r(v.z); v.w = tf32r(v.w);
        reinterpret_cast<float4*>(gate)[tid] = v;
    }
    if (tid < 4) {  // zero K padding [2608:2624)
        float4 z = {0.f, 0.f, 0.f, 0.f};
        reinterpret_cast<float4*>(gate + GATE_IN)[tid] = z;
    }

    const int w = tid >> 5, lane = tid & 31;
    const float* pp[NP] = {p0, p1, p2, p3, p4};
    const size_t base = (size_t)t * (NH * HD) + (size_t)w * HD + lane * 4;

    float4 v[NP];
#pragma unroll
    for (int p = 0; p < NP; p++) v[p] = *reinterpret_cast<const float4*>(pp[p] + base);

    float vals[25];
#pragma unroll
    for (int p = 0; p < NP; p++) {
        vals[p]      = v[p].x + v[p].y + v[p].z + v[p].w;
        vals[5 + p]  = v[p].x * v[p].x + v[p].y * v[p].y + v[p].z * v[p].z + v[p].w * v[p].w;
        vals[10 + p] = fabsf(v[p].x) + fabsf(v[p].y) + fabsf(v[p].z) + fabsf(v[p].w);
    }
    {
        int k = 15;
#pragma unroll
        for (int p = 0; p < NP; p++)
#pragma unroll
            for (int q = p + 1; q < NP; q++)
                vals[k++] = v[p].x * v[q].x + v[p].y * v[q].y + v[p].z * v[q].z + v[p].w * v[q].w;
    }
#pragma unroll
    for (int i = 0; i < 25; i++) vals[i] = wredsum(vals[i]);

    if (lane == 0) {
        const float inv = 1.0f / 128.0f;
        float sq[NP];
#pragma unroll
        for (int p = 0; p < NP; p++) {
            float mean = vals[p] * inv;
            sq[p] = vals[5 + p];
            float l2 = sqrtf(sq[p]);
            float var = sq[p] * inv - mean * mean;
            float am  = vals[10 + p] * inv;
            float* s = gate + HIDDEN + w * (NP * 4) + p * 4;
            s[0] = tf32r(mean); s[1] = tf32r(var); s[2] = tf32r(am); s[3] = tf32r(l2);
            gate[HIDDEN + NH * NP * 4 + w * NP + p] = tf32r(l2);
        }
        int kk = 0;
#pragma unroll
        for (int p = 0; p < NP; p++)
#pragma unroll
            for (int q = p + 1; q < NP; q++) {
                float d2 = sq[p] + sq[q] - 2.0f * vals[15 + kk];
                gate[2448 + w * 10 + kk] = tf32r(sqrtf(fmaxf(d2, 0.0f)));
                kk++;
            }
    }
}

// ---------------------------------------------------------------------------
// W1 repack: [1024, 2608] -> [1024, 2624] zero-padded, tf32-rounded.
// ---------------------------------------------------------------------------
__global__ void pack_w1_kernel(const float* __restrict__ W1)
{
    const int idx = blockIdx.x * 256 + threadIdx.x;
    const int total = GATE_HID * (GATE_IN_PAD / 4);
    if (idx >= total) return;
    const int row = idx / (GATE_IN_PAD / 4);
    const int c4  = idx % (GATE_IN_PAD / 4);
    float4 v = {0.f, 0.f, 0.f, 0.f};
    if (c4 < GATE_IN / 4)
        v = reinterpret_cast<const float4*>(W1 + (size_t)row * GATE_IN)[c4];
    v.x = tf32r(v.x); v.y = tf32r(v.y); v.z = tf32r(v.z); v.w = tf32r(v.w);
    reinterpret_cast<float4*>(g_w1p + (size_t)row * GATE_IN_PAD)[c4] = v;
}

// ---------------------------------------------------------------------------
// Kernel B: GEMM1 via mma.sync tf32.  h = GELU(gate @ W1p^T + b1)
// CTA 128x128, 8 warps (2M x 4N, warp tile 64x32), K double-buffered in
// 32-float chunks via cp.async. Smem rows padded to 36 floats.
// ---------------------------------------------------------------------------
__device__ __forceinline__ void g1_load(uint32_t a_s, uint32_t b_s,
                                        const float* __restrict__ A,
                                        const float* __restrict__ Bm,
                                        int k0, int tid)
{
#pragma unroll
    for (int j = 0; j < 4; j++) {
        const int idx = tid + j * 256;       // 1024 float4 tiles
        const int m  = idx >> 3;
        const int ks = (idx & 7) << 2;
        cp_async16(a_s + (uint32_t)(m * SM_STRIDE + ks) * 4,
                   A + (size_t)m * GATE_IN_PAD + k0 + ks);
        cp_async16(b_s + (uint32_t)(m * SM_STRIDE + ks) * 4,
                   Bm + (size_t)m * GATE_IN_PAD + k0 + ks);
    }
}

__global__ void __launch_bounds__(256, 2) gemm1_mma_kernel(const float* __restrict__ b1)
{
    extern __shared__ float smem[];
    const uint32_t s0 = smem_u32(smem);

    const int tid  = threadIdx.x;
    const int wid  = tid >> 5, lane = tid & 31;
    const int wm   = (wid & 1) * 64;        // warp M origin
    const int wn   = (wid >> 1) * 32;       // warp N origin
    const int g    = lane >> 2;             // groupID 0..7
    const int t    = lane & 3;              // threadID-in-group 0..3

    const float* A  = g_gate + (size_t)blockIdx.y * 128 * GATE_IN_PAD;
    const float* Bm = g_w1p  + (size_t)blockIdx.x * 128 * GATE_IN_PAD;

    float acc[4][4][4];
#pragma unroll
    for (int i = 0; i < 4; i++)
#pragma unroll
        for (int j = 0; j < 4; j++)
#pragma unroll
            for (int r = 0; r < 4; r++) acc[i][j][r] = 0.0f;

    g1_load(s0, s0 + 2 * ABUF_BYTES, A, Bm, 0, tid);
    asm volatile("cp.async.commit_group;" ::: "memory");

    for (int i = 0; i < NCHUNK; i++) {
        const int s = i & 1;
        if (i + 1 < NCHUNK) {
            const int ns = (i + 1) & 1;
            g1_load(s0 + ns * ABUF_BYTES, s0 + (2 + ns) * ABUF_BYTES,
                    A, Bm, (i + 1) * KCHUNK, tid);
        }
        asm volatile("cp.async.commit_group;" ::: "memory");
        if (i + 1 < NCHUNK) asm volatile("cp.async.wait_group 1;" ::: "memory");
        else                asm volatile("cp.async.wait_group 0;" ::: "memory");
        __syncthreads();

        const float* as = smem + s * ABUF_FLOATS;
        const float* bs = smem + (2 + s) * ABUF_FLOATS;

#pragma unroll
        for (int kk = 0; kk < KCHUNK; kk += 8) {
            // PTX m16n8k8 tf32 fragment map (g=lane>>2, t=lane&3):
            //   a0=A[g][t]  a1=A[g+8][t]  a2=A[g][t+4]  a3=A[g+8][t+4]
            //   b0=B[k=t][n=g]  b1=B[k=t+4][n=g]
            uint32_t a[4][4];
#pragma unroll
            for (int mi = 0; mi < 4; mi++) {
                const float* r0 = as + (wm + mi * 16 + g) * SM_STRIDE + kk;
                const float* r1 = as + (wm + mi * 16 + g + 8) * SM_STRIDE + kk;
                a[mi][0] = __float_as_uint(r0[t]);
                a[mi][1] = __float_as_uint(r1[t]);
                a[mi][2] = __float_as_uint(r0[t + 4]);
                a[mi][3] = __float_as_uint(r1[t + 4]);
            }
            uint32_t b[4][2];
#pragma unroll
            for (int nj = 0; nj < 4; nj++) {
                const float* br = bs + (wn + nj * 8 + g) * SM_STRIDE + kk;
                b[nj][0] = __float_as_uint(br[t]);
                b[nj][1] = __float_as_uint(br[t + 4]);
            }
#pragma unroll
            for (int mi = 0; mi < 4; mi++)
#pragma unroll
                for (int nj = 0; nj < 4; nj++)
                    mma_tf32_16x8x8(acc[mi][nj], a[mi][0], a[mi][1], a[mi][2], a[mi][3],
                                    b[nj][0], b[nj][1]);
        }
        __syncthreads();
    }

    // epilogue: bias + exact GELU -> g_h
    // C map: c0=(g,2t) c1=(g,2t+1) c2=(g+8,2t) c3=(g+8,2t+1)
    const size_t row_base = (size_t)blockIdx.y * 128 + wm + g;
    const int    col_base = blockIdx.x * 128 + wn + 2 * t;
#pragma unroll
    for (int nj = 0; nj < 4; nj++) {
        const int gc = col_base + nj * 8;
        const float2 bb = *reinterpret_cast<const float2*>(b1 + gc);
#pragma unroll
        for (int mi = 0; mi < 4; mi++) {
            const size_t r0 = row_base + mi * 16;
            float2 o0, o1;
            o0.x = gelu(acc[mi][nj][0] + bb.x);
            o0.y = gelu(acc[mi][nj][1] + bb.y);
            o1.x = gelu(acc[mi][nj][2] + bb.x);
            o1.y = gelu(acc[mi][nj][3] + bb.y);
            *reinterpret_cast<float2*>(g_h + r0 * GATE_HID + gc)       = o0;
            *reinterpret_cast<float2*>(g_h + (r0 + 8) * GATE_HID + gc) = o1;
        }
    }
}

// ---------------------------------------------------------------------------
// Kernel C: GEMM2 (K=1024, N=80) + softmax/temp + clip(0.02) + renorm.
// ---------------------------------------------------------------------------
__global__ void __launch_bounds__(256) gemm2_softmax_kernel(
    const float* __restrict__ W2, const float* __restrict__ b2,
    const float* __restrict__ log_temp)
{
    __shared__ float hs[TOK][GATE_HID];
    __shared__ float lg[TOK][OUT_DIM];

    const int tid   = threadIdx.x;
    const int tbase = blockIdx.x * TOK;

#pragma unroll
    for (int i = 0; i < TOK; i++)
        reinterpret_cast<float4*>(hs[i])[tid] =
            reinterpret_cast<const float4*>(g_h + (size_t)(tbase + i) * GATE_HID)[tid];
    __syncthreads();

    const int w = tid >> 5, lane = tid & 31;
    for (int j = w; j < OUT_DIM; j += 8) {
        const float4* wr = reinterpret_cast<const float4*>(W2 + (size_t)j * GATE_HID);
        float s0 = 0.f, s1 = 0.f, s2 = 0.f, s3 = 0.f;
#pragma unroll
        for (int i = 0; i < 8; i++) {
            float4 b  = wr[lane + i * 32];
            float4 a0 = reinterpret_cast<float4*>(hs[0])[lane + i * 32];
            float4 a1 = reinterpret_cast<float4*>(hs[1])[lane + i * 32];
            float4 a2 = reinterpret_cast<float4*>(hs[2])[lane + i * 32];
            float4 a3 = reinterpret_cast<float4*>(hs[3])[lane + i * 32];
            s0 += a0.x * b.x + a0.y * b.y + a0.z * b.z + a0.w * b.w;
            s1 += a1.x * b.x + a1.y * b.y + a1.z * b.z + a1.w * b.w;
            s2 += a2.x * b.x + a2.y * b.y + a2.z * b.z + a2.w * b.w;
            s3 += a3.x * b.x + a3.y * b.y + a3.z * b.z + a3.w * b.w;
        }
        s0 = wredsum(s0); s1 = wredsum(s1); s2 = wredsum(s2); s3 = wredsum(s3);
        if (lane == 0) {
            float bj = b2[j];
            lg[0][j] = s0 + bj; lg[1][j] = s1 + bj;
            lg[2][j] = s2 + bj; lg[3][j] = s3 + bj;
        }
    }
    __syncthreads();

    if (tid < TOK * NH) {
        const int tt = tid >> 4, h = tid & 15;
        const float invt = expf(-log_temp[h]);
        float l[NP], mx = -1e30f;
#pragma unroll
        for (int p = 0; p < NP; p++) { l[p] = lg[tt][h * NP + p] * invt; mx = fmaxf(mx, l[p]); }
        float e[NP], se = 0.f;
#pragma unroll
        for (int p = 0; p < NP; p++) { e[p] = expf(l[p] - mx); se += e[p]; }
        const float ise = 1.0f / se;
        float pr[NP], s2s = 0.f;
#pragma unroll
        for (int p = 0; p < NP; p++) { pr[p] = fmaxf(e[p] * ise, 0.02f); s2s += pr[p]; }
        const float is2 = 1.0f / s2s;
        float* dst = g_probs + (size_t)(tbase + tt) * OUT_DIM + h * NP;
#pragma unroll
        for (int p = 0; p < NP; p++) dst[p] = pr[p] * is2;
    }
}

// ---------------------------------------------------------------------------
// Kernel D: weighted path combine.
// ---------------------------------------------------------------------------
__global__ void output_kernel(
    const float* __restrict__ p0, const float* __restrict__ p1,
    const float* __restrict__ p2, const float* __restrict__ p3,
    const float* __restrict__ p4, float* __restrict__ out, int n4)
{
    const int v = blockIdx.x * blockDim.x + threadIdx.x;
    if (v >= n4) return;
    const int t = v >> 9;
    const int h = (v >> 5) & 15;
    const float* pb = g_probs + (size_t)t * OUT_DIM + h * NP;
    const float w0 = pb[0], w1 = pb[1], w2 = pb[2], w3 = pb[3], w4 = pb[4];
    const float4 a0 = reinterpret_cast<const float4*>(p0)[v];
    const float4 a1 = reinterpret_cast<const float4*>(p1)[v];
    const float4 a2 = reinterpret_cast<const float4*>(p2)[v];
    const float4 a3 = reinterpret_cast<const float4*>(p3)[v];
    const float4 a4 = reinterpret_cast<const float4*>(p4)[v];
    float4 o;
    o.x = a0.x * w0 + a1.x * w1 + a2.x * w2 + a3.x * w3 + a4.x * w4;
    o.y = a0.y * w0 + a1.y * w1 + a2.y * w2 + a3.y * w3 + a4.y * w4;
    o.z = a0.z * w0 + a1.z * w1 + a2.z * w2 + a3.z * w3 + a4.z * w4;
    o.w = a0.w * w0 + a1.w * w1 + a2.w * w2 + a3.w * w3 + a4.w * w4;
    reinterpret_cast<float4*>(out)[v] = o;
}

__global__ void zero_tail_kernel(float* out, int start, int total)
{
    const int i = start + blockIdx.x * blockDim.x + threadIdx.x;
    if (i < total) out[i] = 0.0f;
}

// ---------------------------------------------------------------------------
extern "C" void kernel_launch(void* const* d_in, const int* in_sizes, int n_in,
                              void* d_out, int out_size)
{
    const float* hidden = (const float*)d_in[0];
    const float* p0 = (const float*)d_in[1];
    const float* p1 = (const float*)d_in[2];
    const float* p2 = (const float*)d_in[3];
    const float* p3 = (const float*)d_in[4];
    const float* p4 = (const float*)d_in[5];
    const float* W1 = (const float*)d_in[6];
    const float* b1 = (const float*)d_in[7];
    const float* W2 = (const float*)d_in[8];
    const float* b2 = (const float*)d_in[9];
    const float* lt = (const float*)d_in[10];

    const int NT = in_sizes[0] / HIDDEN;   // 8192

    static int smem_set = 0;
    if (!smem_set) {
        cudaFuncSetAttribute(gemm1_mma_kernel,
                             cudaFuncAttributeMaxDynamicSharedMemorySize, GEMM1_SMEM);
        smem_set = 1;
    }

    {
        const int total4 = GATE_HID * (GATE_IN_PAD / 4);
        pack_w1_kernel<<<(total4 + 255) / 256, 256>>>(W1);
    }
    stats_kernel<<<NT, 512>>>(hidden, p0, p1, p2, p3, p4);

    dim3 g1(GATE_HID / 128, NT / 128);   // (8, 64)
    gemm1_mma_kernel<<<g1, 256, GEMM1_SMEM>>>(b1);

    gemm2_softmax_kernel<<<NT / TOK, 256>>>(W2, b2, lt);

    const int n4 = NT * (NH * HD) / 4;
    output_kernel<<<(n4 + 255) / 256, 256>>>(p0, p1, p2, p3, p4, (float*)d_out, n4);

    const int nout = NT * NH * HD;
    if (out_size > nout) {
        const int extra = out_size - nout;
        zero_tail_kernel<<<(extra + 255) / 256, 256>>>((float*)d_out, nout, out_size);
    }
}

// round 5
// speedup vs baseline: 3.0739x; 1.1806x over previous
#include <cuda_runtime.h>
#include <cstdint>
#include <math.h>

#define HIDDEN      2048
#define GATE_IN     2608
#define GATE_IN_PAD 2624        // 82 * 32
#define GATE_HID    1024
#define NH          16
#define HD          128
#define NP          5
#define OUT_DIM     80
#define MAX_NT      8192

// GEMM1 tiling (mma.sync tf32): CTA 128x256, 8 warps of 64x64
#define KCHUNK      32
#define NCHUNK      (GATE_IN_PAD / KCHUNK)   // 82
#define SM_STRIDE   36
#define G1_A_FLOATS (128 * SM_STRIDE)         // 4608
#define G1_B_FLOATS (256 * SM_STRIDE)         // 9216
#define G1_A_BYTES  (G1_A_FLOATS * 4)         // 18432
#define G1_B_BYTES  (G1_B_FLOATS * 4)         // 36864
#define GEMM1_SMEM  (2 * (G1_A_BYTES + G1_B_BYTES))   // 110592

// GEMM2 tiling: CTA 64(M) x 80(N), 8 warps (4M x 2N, warp 16x40), K=1024
#define G2_KC       32
#define G2_NCH      (GATE_HID / G2_KC)        // 32
#define G2_A_FLOATS (64 * SM_STRIDE)          // 2304
#define G2_B_FLOATS (80 * SM_STRIDE)          // 2880
#define GEMM2_SMEM  ((2 * (G2_A_FLOATS + G2_B_FLOATS)) * 4)   // 41472

// Static scratch
__device__ float g_gate[(size_t)MAX_NT * GATE_IN_PAD];
__device__ float g_w1p[(size_t)GATE_HID * GATE_IN_PAD];
__device__ float g_w2p[(size_t)OUT_DIM * GATE_HID];
__device__ float g_h[(size_t)MAX_NT * GATE_HID];
__device__ float g_probs[(size_t)MAX_NT * OUT_DIM];

// ---------------------------------------------------------------------------
// helpers
// ---------------------------------------------------------------------------
__device__ __forceinline__ float wredsum(float v) {
#pragma unroll
    for (int o = 16; o; o >>= 1) v += __shfl_xor_sync(0xffffffffu, v, o);
    return v;
}
__device__ __forceinline__ float tf32r(float x) {
    float y;
    asm("cvt.rna.tf32.f32 %0, %1;" : "=f"(y) : "f"(x));
    return y;
}
__device__ __forceinline__ void cp_async16(uint32_t dst, const void* src) {
    asm volatile("cp.async.cg.shared.global [%0], [%1], 16;" :: "r"(dst), "l"(src));
}
__device__ __forceinline__ uint32_t smem_u32(const void* p) {
    uint32_t a;
    asm("{ .reg .u64 t; cvta.to.shared.u64 t, %1; cvt.u32.u64 %0, t; }" : "=r"(a) : "l"(p));
    return a;
}
__device__ __forceinline__ float gelu(float x) {
    return 0.5f * x * (1.0f + erff(x * 0.70710678118654752f));
}
// PTX m16n8k8 tf32: a0=A[g][t] a1=A[g+8][t] a2=A[g][t+4] a3=A[g+8][t+4]
//                   b0=B[k=t][n=g] b1=B[k=t+4][n=g]
//                   c0=(g,2t) c1=(g,2t+1) c2=(g+8,2t) c3=(g+8,2t+1)
__device__ __forceinline__ void mma_tf32_16x8x8(float c[4],
                                                uint32_t a0, uint32_t a1,
                                                uint32_t a2, uint32_t a3,
                                                uint32_t b0, uint32_t b1) {
    asm("mma.sync.aligned.m16n8k8.row.col.f32.tf32.tf32.f32 "
        "{%0,%1,%2,%3}, {%4,%5,%6,%7}, {%8,%9}, {%0,%1,%2,%3};"
        : "+f"(c[0]), "+f"(c[1]), "+f"(c[2]), "+f"(c[3])
        : "r"(a0), "r"(a1), "r"(a2), "r"(a3), "r"(b0), "r"(b1));
}

// ---------------------------------------------------------------------------
// Kernel A: per-token path stats + gate_input assembly (tf32-rounded).
// ---------------------------------------------------------------------------
__global__ void __launch_bounds__(512) stats_kernel(
    const float* __restrict__ hidden,
    const float* __restrict__ p0, const float* __restrict__ p1,
    const float* __restrict__ p2, const float* __restrict__ p3,
    const float* __restrict__ p4)
{
    const int t   = blockIdx.x;
    const int tid = threadIdx.x;
    float* gate = g_gate + (size_t)t * GATE_IN_PAD;

    {
        float4 v = (reinterpret_cast<const float4*>(hidden) + (size_t)t * (HIDDEN / 4))[tid];
        v.x = tf32r(v.x); v.y = tf32r(v.y); v.z = tf32r(v.z); v.w = tf32r(v.w);
        reinterpret_cast<float4*>(gate)[tid] = v;
    }
    if (tid < 4) {
        float4 z = {0.f, 0.f, 0.f, 0.f};
        reinterpret_cast<float4*>(gate + GATE_IN)[tid] = z;
    }

    const int w = tid >> 5, lane = tid & 31;
    const float* pp[NP] = {p0, p1, p2, p3, p4};
    const size_t base = (size_t)t * (NH * HD) + (size_t)w * HD + lane * 4;

    float4 v[NP];
#pragma unroll
    for (int p = 0; p < NP; p++) v[p] = *reinterpret_cast<const float4*>(pp[p] + base);

    float vals[25];
#pragma unroll
    for (int p = 0; p < NP; p++) {
        vals[p]      = v[p].x + v[p].y + v[p].z + v[p].w;
        vals[5 + p]  = v[p].x * v[p].x + v[p].y * v[p].y + v[p].z * v[p].z + v[p].w * v[p].w;
        vals[10 + p] = fabsf(v[p].x) + fabsf(v[p].y) + fabsf(v[p].z) + fabsf(v[p].w);
    }
    {
        int k = 15;
#pragma unroll
        for (int p = 0; p < NP; p++)
#pragma unroll
            for (int q = p + 1; q < NP; q++)
                vals[k++] = v[p].x * v[q].x + v[p].y * v[q].y + v[p].z * v[q].z + v[p].w * v[q].w;
    }
#pragma unroll
    for (int i = 0; i < 25; i++) vals[i] = wredsum(vals[i]);

    if (lane == 0) {
        const float inv = 1.0f / 128.0f;
        float sq[NP];
#pragma unroll
        for (int p = 0; p < NP; p++) {
            float mean = vals[p] * inv;
            sq[p] = vals[5 + p];
            float l2 = sqrtf(sq[p]);
            float var = sq[p] * inv - mean * mean;
            float am  = vals[10 + p] * inv;
            float* s = gate + HIDDEN + w * (NP * 4) + p * 4;
            s[0] = tf32r(mean); s[1] = tf32r(var); s[2] = tf32r(am); s[3] = tf32r(l2);
            gate[HIDDEN + NH * NP * 4 + w * NP + p] = tf32r(l2);
        }
        int kk = 0;
#pragma unroll
        for (int p = 0; p < NP; p++)
#pragma unroll
            for (int q = p + 1; q < NP; q++) {
                float d2 = sq[p] + sq[q] - 2.0f * vals[15 + kk];
                gate[2448 + w * 10 + kk] = tf32r(sqrtf(fmaxf(d2, 0.0f)));
                kk++;
            }
    }
}

// ---------------------------------------------------------------------------
// Weight repacks (tf32-rounded; W1 zero-padded in K).
// ---------------------------------------------------------------------------
__global__ void pack_w1_kernel(const float* __restrict__ W1)
{
    const int idx = blockIdx.x * 256 + threadIdx.x;
    const int total = GATE_HID * (GATE_IN_PAD / 4);
    if (idx >= total) return;
    const int row = idx / (GATE_IN_PAD / 4);
    const int c4  = idx % (GATE_IN_PAD / 4);
    float4 v = {0.f, 0.f, 0.f, 0.f};
    if (c4 < GATE_IN / 4)
        v = reinterpret_cast<const float4*>(W1 + (size_t)row * GATE_IN)[c4];
    v.x = tf32r(v.x); v.y = tf32r(v.y); v.z = tf32r(v.z); v.w = tf32r(v.w);
    reinterpret_cast<float4*>(g_w1p + (size_t)row * GATE_IN_PAD)[c4] = v;
}

__global__ void pack_w2_kernel(const float* __restrict__ W2)
{
    const int idx = blockIdx.x * 256 + threadIdx.x;   // float4 index
    const int total = OUT_DIM * (GATE_HID / 4);       // 20480
    if (idx >= total) return;
    float4 v = reinterpret_cast<const float4*>(W2)[idx];
    v.x = tf32r(v.x); v.y = tf32r(v.y); v.z = tf32r(v.z); v.w = tf32r(v.w);
    reinterpret_cast<float4*>(g_w2p)[idx] = v;
}

// ---------------------------------------------------------------------------
// Kernel B: GEMM1 via mma.sync tf32.  h = tf32(GELU(gate @ W1p^T + b1))
// CTA 128x256, 8 warps (2M x 4N, warp tile 64x64), K double-buffered.
// ---------------------------------------------------------------------------
__device__ __forceinline__ void g1_load(uint32_t a_s, uint32_t b_s,
                                        const float* __restrict__ A,
                                        const float* __restrict__ Bm,
                                        int k0, int tid)
{
#pragma unroll
    for (int j = 0; j < 4; j++) {                 // A: 128 rows * 8 f4
        const int idx = tid + j * 256;
        const int m  = idx >> 3;
        const int ks = (idx & 7) << 2;
        cp_async16(a_s + (uint32_t)(m * SM_STRIDE + ks) * 4,
                   A + (size_t)m * GATE_IN_PAD + k0 + ks);
    }
#pragma unroll
    for (int j = 0; j < 8; j++) {                 // B: 256 rows * 8 f4
        const int idx = tid + j * 256;
        const int m  = idx >> 3;
        const int ks = (idx & 7) << 2;
        cp_async16(b_s + (uint32_t)(m * SM_STRIDE + ks) * 4,
                   Bm + (size_t)m * GATE_IN_PAD + k0 + ks);
    }
}

__global__ void __launch_bounds__(256, 1) gemm1_mma_kernel(const float* __restrict__ b1)
{
    extern __shared__ float smem[];
    const uint32_t s0 = smem_u32(smem);

    const int tid  = threadIdx.x;
    const int wid  = tid >> 5, lane = tid & 31;
    const int wm   = (wid & 1) * 64;        // warp M origin
    const int wn   = (wid >> 1) * 64;       // warp N origin
    const int g    = lane >> 2;
    const int t    = lane & 3;

    const float* A  = g_gate + (size_t)blockIdx.y * 128 * GATE_IN_PAD;
    const float* Bm = g_w1p  + (size_t)blockIdx.x * 256 * GATE_IN_PAD;

    float acc[4][8][4];
#pragma unroll
    for (int i = 0; i < 4; i++)
#pragma unroll
        for (int j = 0; j < 8; j++)
#pragma unroll
            for (int r = 0; r < 4; r++) acc[i][j][r] = 0.0f;

    g1_load(s0, s0 + 2 * G1_A_BYTES, A, Bm, 0, tid);
    asm volatile("cp.async.commit_group;" ::: "memory");

    for (int i = 0; i < NCHUNK; i++) {
        const int s = i & 1;
        if (i + 1 < NCHUNK) {
            const int ns = (i + 1) & 1;
            g1_load(s0 + ns * G1_A_BYTES, s0 + 2 * G1_A_BYTES + ns * G1_B_BYTES,
                    A, Bm, (i + 1) * KCHUNK, tid);
        }
        asm volatile("cp.async.commit_group;" ::: "memory");
        if (i + 1 < NCHUNK) asm volatile("cp.async.wait_group 1;" ::: "memory");
        else                asm volatile("cp.async.wait_group 0;" ::: "memory");
        __syncthreads();

        const float* as = smem + s * G1_A_FLOATS;
        const float* bs = smem + 2 * G1_A_FLOATS + s * G1_B_FLOATS;

#pragma unroll
        for (int kk = 0; kk < KCHUNK; kk += 8) {
            uint32_t a[4][4];
#pragma unroll
            for (int mi = 0; mi < 4; mi++) {
                const float* r0 = as + (wm + mi * 16 + g) * SM_STRIDE + kk;
                const float* r1 = as + (wm + mi * 16 + g + 8) * SM_STRIDE + kk;
                a[mi][0] = __float_as_uint(r0[t]);
                a[mi][1] = __float_as_uint(r1[t]);
                a[mi][2] = __float_as_uint(r0[t + 4]);
                a[mi][3] = __float_as_uint(r1[t + 4]);
            }
            uint32_t b[8][2];
#pragma unroll
            for (int nj = 0; nj < 8; nj++) {
                const float* br = bs + (wn + nj * 8 + g) * SM_STRIDE + kk;
                b[nj][0] = __float_as_uint(br[t]);
                b[nj][1] = __float_as_uint(br[t + 4]);
            }
#pragma unroll
            for (int mi = 0; mi < 4; mi++)
#pragma unroll
                for (int nj = 0; nj < 8; nj++)
                    mma_tf32_16x8x8(acc[mi][nj], a[mi][0], a[mi][1], a[mi][2], a[mi][3],
                                    b[nj][0], b[nj][1]);
        }
        __syncthreads();
    }

    // epilogue: bias + exact GELU, tf32-rounded (feeds GEMM2 mma) -> g_h
    const size_t row_base = (size_t)blockIdx.y * 128 + wm + g;
    const int    col_base = blockIdx.x * 256 + wn + 2 * t;
#pragma unroll
    for (int nj = 0; nj < 8; nj++) {
        const int gc = col_base + nj * 8;
        const float2 bb = *reinterpret_cast<const float2*>(b1 + gc);
#pragma unroll
        for (int mi = 0; mi < 4; mi++) {
            const size_t r0 = row_base + mi * 16;
            float2 o0, o1;
            o0.x = tf32r(gelu(acc[mi][nj][0] + bb.x));
            o0.y = tf32r(gelu(acc[mi][nj][1] + bb.y));
            o1.x = tf32r(gelu(acc[mi][nj][2] + bb.x));
            o1.y = tf32r(gelu(acc[mi][nj][3] + bb.y));
            *reinterpret_cast<float2*>(g_h + r0 * GATE_HID + gc)       = o0;
            *reinterpret_cast<float2*>(g_h + (r0 + 8) * GATE_HID + gc) = o1;
        }
    }
}

// ---------------------------------------------------------------------------
// Kernel C: GEMM2 via mma.sync tf32 + fused bias/softmax/clip/renorm.
// CTA: 64 tokens x 80 outputs. 8 warps: 4 M-warps (16 rows) x 2 N-warps (40).
// ---------------------------------------------------------------------------
__global__ void __launch_bounds__(256) gemm2_mma_kernel(
    const float* __restrict__ b2, const float* __restrict__ log_temp)
{
    extern __shared__ float smem[];
    const uint32_t s0 = smem_u32(smem);

    const int tid  = threadIdx.x;
    const int wid  = tid >> 5, lane = tid & 31;
    const int mw   = wid >> 1;             // 0..3  (M origin = mw*16)
    const int nw   = wid & 1;              // 0..1  (N origin = nw*40)
    const int g    = lane >> 2;
    const int t    = lane & 3;

    const int tbase = blockIdx.x * 64;
    const float* A = g_h + (size_t)tbase * GATE_HID;

    float acc[5][4];
#pragma unroll
    for (int j = 0; j < 5; j++)
#pragma unroll
        for (int r = 0; r < 4; r++) acc[j][r] = 0.0f;

    // staged smem: A0, A1, B0, B1 (floats)
    const uint32_t aoff[2] = {0u, (uint32_t)G2_A_FLOATS * 4};
    const uint32_t boff[2] = {(uint32_t)(2 * G2_A_FLOATS) * 4,
                              (uint32_t)(2 * G2_A_FLOATS + G2_B_FLOATS) * 4};

    // prologue
    {
#pragma unroll
        for (int j = 0; j < 2; j++) {          // A: 64 rows * 8 f4 = 512
            const int idx = tid + j * 256;
            const int m = idx >> 3, ks = (idx & 7) << 2;
            cp_async16(s0 + aoff[0] + (uint32_t)(m * SM_STRIDE + ks) * 4,
                       A + (size_t)m * GATE_HID + ks);
        }
#pragma unroll
        for (int j = 0; j < 3; j++) {          // B: 80 rows * 8 f4 = 640
            const int idx = tid + j * 256;
            if (idx < 640) {
                const int m = idx >> 3, ks = (idx & 7) << 2;
                cp_async16(s0 + boff[0] + (uint32_t)(m * SM_STRIDE + ks) * 4,
                           g_w2p + (size_t)m * GATE_HID + ks);
            }
        }
        asm volatile("cp.async.commit_group;" ::: "memory");
    }

    for (int i = 0; i < G2_NCH; i++) {
        const int s = i & 1;
        if (i + 1 < G2_NCH) {
            const int ns = (i + 1) & 1;
            const int k0 = (i + 1) * G2_KC;
#pragma unroll
            for (int j = 0; j < 2; j++) {
                const int idx = tid + j * 256;
                const int m = idx >> 3, ks = (idx & 7) << 2;
                cp_async16(s0 + aoff[ns] + (uint32_t)(m * SM_STRIDE + ks) * 4,
                           A + (size_t)m * GATE_HID + k0 + ks);
            }
#pragma unroll
            for (int j = 0; j < 3; j++) {
                const int idx = tid + j * 256;
                if (idx < 640) {
                    const int m = idx >> 3, ks = (idx & 7) << 2;
                    cp_async16(s0 + boff[ns] + (uint32_t)(m * SM_STRIDE + ks) * 4,
                               g_w2p + (size_t)m * GATE_HID + k0 + ks);
                }
            }
        }
        asm volatile("cp.async.commit_group;" ::: "memory");
        if (i + 1 < G2_NCH) asm volatile("cp.async.wait_group 1;" ::: "memory");
        else                asm volatile("cp.async.wait_group 0;" ::: "memory");
        __syncthreads();

        const float* as = smem + (s ? G2_A_FLOATS : 0);
        const float* bs = smem + 2 * G2_A_FLOATS + (s ? G2_B_FLOATS : 0);

#pragma unroll
        for (int kk = 0; kk < G2_KC; kk += 8) {
            const float* r0 = as + (mw * 16 + g) * SM_STRIDE + kk;
            const float* r1 = as + (mw * 16 + g + 8) * SM_STRIDE + kk;
            uint32_t a0 = __float_as_uint(r0[t]);
            uint32_t a1 = __float_as_uint(r1[t]);
            uint32_t a2 = __float_as_uint(r0[t + 4]);
            uint32_t a3 = __float_as_uint(r1[t + 4]);
#pragma unroll
            for (int nj = 0; nj < 5; nj++) {
                const float* br = bs + (nw * 40 + nj * 8 + g) * SM_STRIDE + kk;
                mma_tf32_16x8x8(acc[nj], a0, a1, a2, a3,
                                __float_as_uint(br[t]), __float_as_uint(br[t + 4]));
            }
        }
        __syncthreads();
    }

    // logits -> smem lg[64][80] (reuse stage memory)
    float* lg = smem;
    {
        const int r0 = mw * 16 + g;
        const int c0 = nw * 40 + 2 * t;
#pragma unroll
        for (int nj = 0; nj < 5; nj++) {
            const int c = c0 + nj * 8;
            lg[r0 * OUT_DIM + c]            = acc[nj][0];
            lg[r0 * OUT_DIM + c + 1]        = acc[nj][1];
            lg[(r0 + 8) * OUT_DIM + c]      = acc[nj][2];
            lg[(r0 + 8) * OUT_DIM + c + 1]  = acc[nj][3];
        }
    }
    __syncthreads();

    // softmax per (token, head): 64*16 = 1024 groups, 4 per thread
#pragma unroll
    for (int it = 0; it < 4; it++) {
        const int idx = tid + it * 256;
        const int tt = idx >> 4, h = idx & 15;
        const float invt = expf(-log_temp[h]);
        float l[NP], mx = -1e30f;
#pragma unroll
        for (int p = 0; p < NP; p++) {
            l[p] = (lg[tt * OUT_DIM + h * NP + p] + __ldg(b2 + h * NP + p)) * invt;
            mx = fmaxf(mx, l[p]);
        }
        float e[NP], se = 0.f;
#pragma unroll
        for (int p = 0; p < NP; p++) { e[p] = expf(l[p] - mx); se += e[p]; }
        const float ise = 1.0f / se;
        float pr[NP], s2s = 0.f;
#pragma unroll
        for (int p = 0; p < NP; p++) { pr[p] = fmaxf(e[p] * ise, 0.02f); s2s += pr[p]; }
        const float is2 = 1.0f / s2s;
        float* dst = g_probs + (size_t)(tbase + tt) * OUT_DIM + h * NP;
#pragma unroll
        for (int p = 0; p < NP; p++) dst[p] = pr[p] * is2;
    }
}

// ---------------------------------------------------------------------------
// Kernel D: weighted path combine.
// ---------------------------------------------------------------------------
__global__ void output_kernel(
    const float* __restrict__ p0, const float* __restrict__ p1,
    const float* __restrict__ p2, const float* __restrict__ p3,
    const float* __restrict__ p4, float* __restrict__ out, int n4)
{
    const int v = blockIdx.x * blockDim.x + threadIdx.x;
    if (v >= n4) return;
    const int t = v >> 9;
    const int h = (v >> 5) & 15;
    const float* pb = g_probs + (size_t)t * OUT_DIM + h * NP;
    const float w0 = pb[0], w1 = pb[1], w2 = pb[2], w3 = pb[3], w4 = pb[4];
    const float4 a0 = reinterpret_cast<const float4*>(p0)[v];
    const float4 a1 = reinterpret_cast<const float4*>(p1)[v];
    const float4 a2 = reinterpret_cast<const float4*>(p2)[v];
    const float4 a3 = reinterpret_cast<const float4*>(p3)[v];
    const float4 a4 = reinterpret_cast<const float4*>(p4)[v];
    float4 o;
    o.x = a0.x * w0 + a1.x * w1 + a2.x * w2 + a3.x * w3 + a4.x * w4;
    o.y = a0.y * w0 + a1.y * w1 + a2.y * w2 + a3.y * w3 + a4.y * w4;
    o.z = a0.z * w0 + a1.z * w1 + a2.z * w2 + a3.z * w3 + a4.z * w4;
    o.w = a0.w * w0 + a1.w * w1 + a2.w * w2 + a3.w * w3 + a4.w * w4;
    reinterpret_cast<float4*>(out)[v] = o;
}

__global__ void zero_tail_kernel(float* out, int start, int total)
{
    const int i = start + blockIdx.x * blockDim.x + threadIdx.x;
    if (i < total) out[i] = 0.0f;
}

// ---------------------------------------------------------------------------
extern "C" void kernel_launch(void* const* d_in, const int* in_sizes, int n_in,
                              void* d_out, int out_size)
{
    const float* hidden = (const float*)d_in[0];
    const float* p0 = (const float*)d_in[1];
    const float* p1 = (const float*)d_in[2];
    const float* p2 = (const float*)d_in[3];
    const float* p3 = (const float*)d_in[4];
    const float* p4 = (const float*)d_in[5];
    const float* W1 = (const float*)d_in[6];
    const float* b1 = (const float*)d_in[7];
    const float* W2 = (const float*)d_in[8];
    const float* b2 = (const float*)d_in[9];
    const float* lt = (const float*)d_in[10];

    const int NT = in_sizes[0] / HIDDEN;   // 8192

    static int smem_set = 0;
    if (!smem_set) {
        cudaFuncSetAttribute(gemm1_mma_kernel,
                             cudaFuncAttributeMaxDynamicSharedMemorySize, GEMM1_SMEM);
        cudaFuncSetAttribute(gemm2_mma_kernel,
                             cudaFuncAttributeMaxDynamicSharedMemorySize, GEMM2_SMEM);
        smem_set = 1;
    }

    {
        const int t1 = GATE_HID * (GATE_IN_PAD / 4);
        pack_w1_kernel<<<(t1 + 255) / 256, 256>>>(W1);
        const int t2 = OUT_DIM * (GATE_HID / 4);
        pack_w2_kernel<<<(t2 + 255) / 256, 256>>>(W2);
    }
    stats_kernel<<<NT, 512>>>(hidden, p0, p1, p2, p3, p4);

    dim3 g1(GATE_HID / 256, NT / 128);   // (4, 64)
    gemm1_mma_kernel<<<g1, 256, GEMM1_SMEM>>>(b1);

    gemm2_mma_kernel<<<NT / 64, 256, GEMM2_SMEM>>>(b2, lt);

    const int n4 = NT * (NH * HD) / 4;
    output_kernel<<<(n4 + 255) / 256, 256>>>(p0, p1, p2, p3, p4, (float*)d_out, n4);

    const int nout = NT * NH * HD;
    if (out_size > nout) {
        const int extra = out_size - nout;
        zero_tail_kernel<<<(extra + 255) / 256, 256>>>((float*)d_out, nout, out_size);
    }
}